// round 1
// baseline (speedup 1.0000x reference)
#include <cuda_runtime.h>
#include <math.h>

#define N_NODES 100000
#define N_EDGES 3200000
#define N_GRAPHS 64

// ---------------- scratch (device globals: no runtime allocation allowed) ----
__device__ __align__(16) float g_deg_out[N_NODES];   // -> norm_src after k_norm
__device__ __align__(16) float g_deg_in [N_NODES];   // -> norm_dst after k_norm
__device__ __align__(16) float g_t [N_NODES * 64];   // messages to scatter
__device__ __align__(16) float g_m [N_NODES * 64];   // aggregation buffer
__device__ __align__(16) float g_h [N_NODES * 128];  // activations
__device__ __align__(16) float g_hg[N_GRAPHS * 64];  // pooled graph features

// ---------------- zero kernels ----------------------------------------------
__global__ void k_zero_misc() {
    int i = blockIdx.x * blockDim.x + threadIdx.x;
    if (i < N_NODES) { g_deg_out[i] = 0.f; g_deg_in[i] = 0.f; }
    if (i < N_GRAPHS * 64) g_hg[i] = 0.f;
}

__global__ void k_zero_m() {
    const int n4 = N_NODES * 16;  // g_m as float4
    int i = blockIdx.x * blockDim.x + threadIdx.x;
    float4 z = make_float4(0.f, 0.f, 0.f, 0.f);
    for (; i < n4; i += gridDim.x * blockDim.x)
        reinterpret_cast<float4*>(g_m)[i] = z;
}

// ---------------- degrees + norms --------------------------------------------
__global__ void k_degree(const int* __restrict__ src, const int* __restrict__ dst) {
    int i = blockIdx.x * blockDim.x + threadIdx.x;
    if (i < N_EDGES) {
        atomicAdd(&g_deg_out[src[i]], 1.f);
        atomicAdd(&g_deg_in [dst[i]], 1.f);
    }
}

__global__ void k_norm() {
    int i = blockIdx.x * blockDim.x + threadIdx.x;
    if (i < N_NODES) {
        g_deg_out[i] = rsqrtf(fmaxf(g_deg_out[i], 1.f));
        g_deg_in [i] = rsqrtf(fmaxf(g_deg_in [i], 1.f));
    }
}

// ---------------- fused (row-scale) x matmul ---------------------------------
// out[n, j] = act( (X[n,:] * scale[n]) @ W + bias[j] )
template <int DIN, int DOUT, bool RELU, bool HASBIAS>
__global__ void k_mm(const float* __restrict__ X, const float* __restrict__ scale,
                     const float* __restrict__ W, const float* __restrict__ bias,
                     float* __restrict__ out) {
    constexpr int NPB = 256 / DOUT;  // nodes per iteration
    __shared__ float sW[DIN * DOUT];
    __shared__ float sX[NPB][DIN];

    for (int i = threadIdx.x; i < DIN * DOUT; i += 256) sW[i] = W[i];

    const int j  = threadIdx.x % DOUT;
    const int nl = threadIdx.x / DOUT;
    float bj = 0.f;
    if (HASBIAS) bj = bias[j];

    for (int base = blockIdx.x * NPB; base < N_NODES; base += gridDim.x * NPB) {
        __syncthreads();
        for (int i = threadIdx.x; i < NPB * DIN; i += 256) {
            int n = base + i / DIN;
            sX[i / DIN][i % DIN] =
                (n < N_NODES) ? X[(size_t)n * DIN + (i % DIN)] * scale[n] : 0.f;
        }
        __syncthreads();
        int n = base + nl;
        if (n < N_NODES) {
            float acc = bj;
#pragma unroll
            for (int k = 0; k < DIN; k++)
                acc = fmaf(sX[nl][k], sW[k * DOUT + j], acc);
            if (RELU) acc = fmaxf(acc, 0.f);
            out[(size_t)n * DOUT + j] = acc;
        }
    }
}

// ---------------- edge scatter: m[dst] += t[src]  (64 floats / edge) ---------
__global__ void k_scatter(const int* __restrict__ src, const int* __restrict__ dst) {
    unsigned gt = blockIdx.x * blockDim.x + threadIdx.x;
    unsigned e = gt >> 4;       // 16 threads per edge
    if (e >= N_EDGES) return;
    unsigned q = gt & 15;       // which float4 of the 64-float row
    int s = __ldg(&src[e]);
    int d = __ldg(&dst[e]);
    float4 v = reinterpret_cast<const float4*>(g_t)[(size_t)s * 16 + q];
    float* p = g_m + (size_t)d * 64 + q * 4;
    asm volatile("red.global.add.v4.f32 [%0], {%1,%2,%3,%4};"
                 :: "l"(p), "f"(v.x), "f"(v.y), "f"(v.z), "f"(v.w)
                 : "memory");
}

// ---------------- per-node epilogue: relu(m*norm_dst + b) [* norm_src] -------
__global__ void k_finish(const float* __restrict__ b, int apply_out_scale,
                         float* __restrict__ out) {
    int i = blockIdx.x * blockDim.x + threadIdx.x;  // over N_NODES*64
    if (i >= N_NODES * 64) return;
    int n = i >> 6, j = i & 63;
    float v = fmaxf(g_m[i] * g_deg_in[n] + b[j], 0.f);
    if (apply_out_scale) v *= g_deg_out[n];  // fold norm_src of next layer
    out[i] = v;
}

// ---------------- graph pooling (graph_ids sorted) ---------------------------
__global__ void k_pool(const float* __restrict__ h, const int* __restrict__ gid) {
    int f = threadIdx.x & 63;
    int r = threadIdx.x >> 6;           // 0..3
    int start = blockIdx.x * 512;
    int end = min(start + 512, N_NODES);
    float acc = 0.f;
    int cur = -1;
    for (int n = start + r; n < end; n += 4) {
        int g = gid[n];
        if (g != cur) {
            if (cur >= 0) atomicAdd(&g_hg[cur * 64 + f], acc);
            cur = g; acc = 0.f;
        }
        acc += h[(size_t)n * 64 + f];
    }
    if (cur >= 0) atomicAdd(&g_hg[cur * 64 + f], acc);
}

// ---------------- head: out = tanh(hg) @ Wd + bd -----------------------------
__global__ void k_final(const float* __restrict__ Wd, const float* __restrict__ bd,
                        float* __restrict__ out) {
    int t = threadIdx.x;
    if (t >= N_GRAPHS * 10) return;
    int g = t / 10, c = t % 10;
    float acc = bd[c];
#pragma unroll 8
    for (int k = 0; k < 64; k++)
        acc += tanhf(g_hg[g * 64 + k]) * Wd[k * 10 + c];
    out[t] = acc;
}

// ---------------- host orchestration -----------------------------------------
extern "C" void kernel_launch(void* const* d_in, const int* in_sizes, int n_in,
                              void* d_out, int out_size) {
    const float* in_feat = (const float*)d_in[0];
    const int*   src     = (const int*)  d_in[1];
    const int*   dst     = (const int*)  d_in[2];
    const int*   gid     = (const int*)  d_in[3];
    const float* W1 = (const float*)d_in[4];
    const float* b1 = (const float*)d_in[5];
    const float* W2 = (const float*)d_in[6];
    const float* b2 = (const float*)d_in[7];
    const float* W3 = (const float*)d_in[8];
    const float* b3 = (const float*)d_in[9];
    const float* Wd = (const float*)d_in[10];
    const float* bd = (const float*)d_in[11];
    float* out = (float*)d_out;

    float *p_t, *p_h, *p_m, *p_ns, *p_nd;
    cudaGetSymbolAddress((void**)&p_t,  g_t);
    cudaGetSymbolAddress((void**)&p_h,  g_h);
    cudaGetSymbolAddress((void**)&p_m,  g_m);
    cudaGetSymbolAddress((void**)&p_ns, g_deg_out);
    cudaGetSymbolAddress((void**)&p_nd, g_deg_in);

    const int TPB = 256;
    const int scat_blocks = (N_EDGES * 16 + TPB - 1) / TPB;   // 200000
    const int fin_blocks  = (N_NODES * 64 + TPB - 1) / TPB;   // 25000
    const int MM_GRID = 1184;                                 // ~8 blocks/SM

    // degrees + norms + initial zeroing
    k_zero_misc<<<(N_NODES + TPB - 1) / TPB, TPB>>>();
    k_zero_m<<<4096, TPB>>>();
    k_degree<<<(N_EDGES + TPB - 1) / TPB, TPB>>>(src, dst);
    k_norm<<<(N_NODES + TPB - 1) / TPB, TPB>>>();

    // ---- Layer 1: 128 -> 64, W applied BEFORE aggregation ----
    k_mm<128, 64, false, false><<<MM_GRID, TPB>>>(in_feat, p_ns, W1, nullptr, p_t);
    k_scatter<<<scat_blocks, TPB>>>(src, dst);
    k_finish<<<fin_blocks, TPB>>>(b1, /*apply_out_scale=*/1, p_t);

    // ---- Layer 2: 64 -> 128, aggregate FIRST, then W ----
    k_zero_m<<<4096, TPB>>>();
    k_scatter<<<scat_blocks, TPB>>>(src, dst);
    k_mm<64, 128, true, true><<<MM_GRID, TPB>>>(p_m, p_nd, W2, b2, p_h);

    // ---- Layer 3: 128 -> 64, W applied BEFORE aggregation ----
    k_mm<128, 64, false, false><<<MM_GRID, TPB>>>(p_h, p_ns, W3, nullptr, p_t);
    k_zero_m<<<4096, TPB>>>();
    k_scatter<<<scat_blocks, TPB>>>(src, dst);
    k_finish<<<fin_blocks, TPB>>>(b3, /*apply_out_scale=*/0, p_h);

    // ---- pooling + head ----
    k_pool<<<(N_NODES + 511) / 512, TPB>>>(p_h, gid);
    k_final<<<1, N_GRAPHS * 10>>>(Wd, bd, out);
}

// round 2
// speedup vs baseline: 1.4506x; 1.4506x over previous
#include <cuda_runtime.h>
#include <math.h>

#define N_NODES 100000
#define N_EDGES 3200000
#define N_GRAPHS 64
#define NBLK 391                    // ceil(N_NODES/256)

// ---------------- scratch (device globals; no runtime allocation) ------------
__device__ __align__(16) int   g_cnt_in [N_NODES];
__device__ __align__(16) int   g_cnt_out[N_NODES];
__device__ __align__(16) int   g_fill   [N_NODES];
__device__ __align__(16) int   g_local  [N_NODES];      // per-block exclusive scan
__device__ __align__(16) int   g_blksum [512];
__device__ __align__(16) int   g_rowptr [N_NODES + 1];
__device__ __align__(16) int   g_srcsrt [N_EDGES];      // src ids grouped by dst
__device__ __align__(16) float g_ns [N_NODES];          // norm_src
__device__ __align__(16) float g_nd [N_NODES];          // norm_dst
__device__ __align__(16) float g_t  [N_NODES * 64];     // messages
__device__ __align__(16) float g_m  [N_NODES * 64];     // aggregated / activations
__device__ __align__(16) float g_h  [N_NODES * 128];    // 128-wide activations
__device__ __align__(16) float g_hg [N_GRAPHS * 64];    // pooled graph features

// ---------------- zero ---------------------------------------------------------
__global__ void k_zero() {
    int i = blockIdx.x * blockDim.x + threadIdx.x;
    if (i < N_NODES) { g_cnt_in[i] = 0; g_cnt_out[i] = 0; g_fill[i] = 0; }
    if (i < N_GRAPHS * 64) g_hg[i] = 0.f;
}

// ---------------- degree histograms --------------------------------------------
__global__ void k_hist(const int* __restrict__ src, const int* __restrict__ dst) {
    int i = blockIdx.x * blockDim.x + threadIdx.x;
    if (i < N_EDGES) {
        atomicAdd(&g_cnt_in [dst[i]], 1);
        atomicAdd(&g_cnt_out[src[i]], 1);
    }
}

// ---------------- 2-level exclusive scan of g_cnt_in → g_rowptr ----------------
__global__ void k_scan1() {
    __shared__ int sh[256];
    int i = blockIdx.x * 256 + threadIdx.x;
    int v = (i < N_NODES) ? g_cnt_in[i] : 0;
    sh[threadIdx.x] = v;
    __syncthreads();
#pragma unroll
    for (int off = 1; off < 256; off <<= 1) {
        int t = (threadIdx.x >= off) ? sh[threadIdx.x - off] : 0;
        __syncthreads();
        sh[threadIdx.x] += t;
        __syncthreads();
    }
    if (i < N_NODES) g_local[i] = sh[threadIdx.x] - v;   // exclusive
    if (threadIdx.x == 255) g_blksum[blockIdx.x] = sh[255];
}

__global__ void k_scan2() {
    __shared__ int sh[512];
    int t = threadIdx.x;
    int v = (t < NBLK) ? g_blksum[t] : 0;
    sh[t] = v;
    __syncthreads();
#pragma unroll
    for (int off = 1; off < 512; off <<= 1) {
        int u = (t >= off) ? sh[t - off] : 0;
        __syncthreads();
        sh[t] += u;
        __syncthreads();
    }
    if (t < NBLK) g_blksum[t] = sh[t] - v;               // exclusive
}

__global__ void k_scan3() {
    int i = blockIdx.x * 256 + threadIdx.x;
    if (i < N_NODES) g_rowptr[i] = g_local[i] + g_blksum[blockIdx.x];
    if (i == 0) g_rowptr[N_NODES] = N_EDGES;
}

// ---------------- bucket fill: src ids grouped by dst ---------------------------
__global__ void k_fill(const int* __restrict__ src, const int* __restrict__ dst) {
    int i = blockIdx.x * blockDim.x + threadIdx.x;
    if (i < N_EDGES) {
        int d = dst[i];
        int pos = g_rowptr[d] + atomicAdd(&g_fill[d], 1);
        g_srcsrt[pos] = src[i];
    }
}

// ---------------- norms ---------------------------------------------------------
__global__ void k_norm() {
    int i = blockIdx.x * blockDim.x + threadIdx.x;
    if (i < N_NODES) {
        g_ns[i] = rsqrtf(fmaxf((float)g_cnt_out[i], 1.f));
        g_nd[i] = rsqrtf(fmaxf((float)g_cnt_in [i], 1.f));
    }
}

// ---------------- fused (row-scale) x matmul ------------------------------------
// out[n, j] = act( (X[n,:] * scale[n]) @ W + bias[j] )
template <int DIN, int DOUT, bool RELU, bool HASBIAS>
__global__ void k_mm(const float* __restrict__ X, const float* __restrict__ scale,
                     const float* __restrict__ W, const float* __restrict__ bias,
                     float* __restrict__ out) {
    constexpr int NPB = 256 / DOUT;
    __shared__ float sW[DIN * DOUT];
    __shared__ float sX[NPB][DIN];

    for (int i = threadIdx.x; i < DIN * DOUT; i += 256) sW[i] = W[i];

    const int j  = threadIdx.x % DOUT;
    const int nl = threadIdx.x / DOUT;
    float bj = 0.f;
    if (HASBIAS) bj = bias[j];

    for (int base = blockIdx.x * NPB; base < N_NODES; base += gridDim.x * NPB) {
        __syncthreads();
        for (int i = threadIdx.x; i < NPB * DIN; i += 256) {
            int n = base + i / DIN;
            sX[i / DIN][i % DIN] =
                (n < N_NODES) ? X[(size_t)n * DIN + (i % DIN)] * scale[n] : 0.f;
        }
        __syncthreads();
        int n = base + nl;
        if (n < N_NODES) {
            float acc = bj;
#pragma unroll
            for (int k = 0; k < DIN; k++)
                acc = fmaf(sX[nl][k], sW[k * DOUT + j], acc);
            if (RELU) acc = fmaxf(acc, 0.f);
            out[(size_t)n * DOUT + j] = acc;
        }
    }
}

// ---------------- CSR gather + fused epilogue ------------------------------------
// MODE 0: out = sum                         (raw aggregation)
// MODE 1: out = relu(sum*nd + b) * ns       (layer epilogue + fold next norm_src)
// MODE 2: out = relu(sum*nd + b)            (final layer epilogue)
template <int MODE>
__global__ void k_gather(const float* __restrict__ tin, const float* __restrict__ bias,
                         float* __restrict__ outp) {
    const int q   = threadIdx.x & 15;            // float4 column within 64-float row
    const int n   = blockIdx.x * 16 + (threadIdx.x >> 4);
    const unsigned gmask = 0xFFFFu << (threadIdx.x & 16);

    int beg = __ldg(&g_rowptr[n]);
    int end = __ldg(&g_rowptr[n + 1]);

    const float4* t4 = (const float4*)tin;
    float4 acc = make_float4(0.f, 0.f, 0.f, 0.f);

    int e = beg;
    for (; e + 2 <= end; e += 2) {
        int sv = 0;
        if (q < 2) sv = __ldg(&g_srcsrt[e + q]);
        int s0 = __shfl_sync(gmask, sv, 0, 16);
        int s1 = __shfl_sync(gmask, sv, 1, 16);
        float4 v0 = __ldg(&t4[(size_t)s0 * 16 + q]);
        float4 v1 = __ldg(&t4[(size_t)s1 * 16 + q]);
        acc.x += v0.x; acc.y += v0.y; acc.z += v0.z; acc.w += v0.w;
        acc.x += v1.x; acc.y += v1.y; acc.z += v1.z; acc.w += v1.w;
    }
    if (e < end) {
        int sv = 0;
        if (q == 0) sv = __ldg(&g_srcsrt[e]);
        int s0 = __shfl_sync(gmask, sv, 0, 16);
        float4 v0 = __ldg(&t4[(size_t)s0 * 16 + q]);
        acc.x += v0.x; acc.y += v0.y; acc.z += v0.z; acc.w += v0.w;
    }

    if (MODE == 0) {
        ((float4*)outp)[(size_t)n * 16 + q] = acc;
    } else {
        float nd = g_nd[n];
        float4 b = ((const float4*)bias)[q];
        float4 r;
        r.x = fmaxf(acc.x * nd + b.x, 0.f);
        r.y = fmaxf(acc.y * nd + b.y, 0.f);
        r.z = fmaxf(acc.z * nd + b.z, 0.f);
        r.w = fmaxf(acc.w * nd + b.w, 0.f);
        if (MODE == 1) {
            float ns = g_ns[n];
            r.x *= ns; r.y *= ns; r.z *= ns; r.w *= ns;
        }
        ((float4*)outp)[(size_t)n * 16 + q] = r;
    }
}

// ---------------- graph pooling (graph_ids sorted) -------------------------------
__global__ void k_pool(const float* __restrict__ h, const int* __restrict__ gid) {
    int f = threadIdx.x & 63;
    int r = threadIdx.x >> 6;
    int start = blockIdx.x * 512;
    int end = min(start + 512, N_NODES);
    float acc = 0.f;
    int cur = -1;
    for (int n = start + r; n < end; n += 4) {
        int g = gid[n];
        if (g != cur) {
            if (cur >= 0) atomicAdd(&g_hg[cur * 64 + f], acc);
            cur = g; acc = 0.f;
        }
        acc += h[(size_t)n * 64 + f];
    }
    if (cur >= 0) atomicAdd(&g_hg[cur * 64 + f], acc);
}

// ---------------- head: out = tanh(hg) @ Wd + bd ---------------------------------
__global__ void k_final(const float* __restrict__ Wd, const float* __restrict__ bd,
                        float* __restrict__ out) {
    int t = threadIdx.x;
    if (t >= N_GRAPHS * 10) return;
    int g = t / 10, c = t % 10;
    float acc = bd[c];
#pragma unroll 8
    for (int k = 0; k < 64; k++)
        acc += tanhf(g_hg[g * 64 + k]) * Wd[k * 10 + c];
    out[t] = acc;
}

// ---------------- host orchestration ----------------------------------------------
extern "C" void kernel_launch(void* const* d_in, const int* in_sizes, int n_in,
                              void* d_out, int out_size) {
    const float* in_feat = (const float*)d_in[0];
    const int*   src     = (const int*)  d_in[1];
    const int*   dst     = (const int*)  d_in[2];
    const int*   gid     = (const int*)  d_in[3];
    const float* W1 = (const float*)d_in[4];
    const float* b1 = (const float*)d_in[5];
    const float* W2 = (const float*)d_in[6];
    const float* b2 = (const float*)d_in[7];
    const float* W3 = (const float*)d_in[8];
    const float* b3 = (const float*)d_in[9];
    const float* Wd = (const float*)d_in[10];
    const float* bd = (const float*)d_in[11];
    float* out = (float*)d_out;

    float *p_t, *p_h, *p_m, *p_ns, *p_nd;
    cudaGetSymbolAddress((void**)&p_t,  g_t);
    cudaGetSymbolAddress((void**)&p_h,  g_h);
    cudaGetSymbolAddress((void**)&p_m,  g_m);
    cudaGetSymbolAddress((void**)&p_ns, g_ns);
    cudaGetSymbolAddress((void**)&p_nd, g_nd);

    const int TPB = 256;
    const int EDGE_BLKS = (N_EDGES + TPB - 1) / TPB;      // 12500
    const int GATH_BLKS = N_NODES / 16;                   // 6250 (exact)
    const int MM_GRID = 1184;

    // ---- CSR build (reused by all 3 layers) ----
    k_zero <<<NBLK, TPB>>>();
    k_hist <<<EDGE_BLKS, TPB>>>(src, dst);
    k_scan1<<<NBLK, TPB>>>();
    k_scan2<<<1, 512>>>();
    k_scan3<<<NBLK, TPB>>>();
    k_fill <<<EDGE_BLKS, TPB>>>(src, dst);
    k_norm <<<NBLK, TPB>>>();

    // ---- Layer 1: 128 -> 64, W before aggregation ----
    k_mm<128, 64, false, false><<<MM_GRID, TPB>>>(in_feat, p_ns, W1, nullptr, p_t);
    k_gather<1><<<GATH_BLKS, TPB>>>(p_t, b1, p_m);        // g_m = relu(agg*nd+b1)*ns

    // ---- Layer 2: 64 -> 128, aggregate first ----
    k_gather<0><<<GATH_BLKS, TPB>>>(p_m, nullptr, p_t);   // g_t = agg
    k_mm<64, 128, true, true><<<MM_GRID, TPB>>>(p_t, p_nd, W2, b2, p_h);

    // ---- Layer 3: 128 -> 64, W before aggregation ----
    k_mm<128, 64, false, false><<<MM_GRID, TPB>>>(p_h, p_ns, W3, nullptr, p_t);
    k_gather<2><<<GATH_BLKS, TPB>>>(p_t, b3, p_m);        // g_m = relu(agg*nd+b3)

    // ---- pooling + head ----
    k_pool <<<(N_NODES + 511) / 512, TPB>>>(p_m, gid);
    k_final<<<1, N_GRAPHS * 10>>>(Wd, bd, out);
}

// round 3
// speedup vs baseline: 2.3802x; 1.6408x over previous
#include <cuda_runtime.h>
#include <math.h>

#define N_NODES 100000
#define N_EDGES 3200000
#define N_GRAPHS 64
#define NBLK 391                    // ceil(N_NODES/256)

// ---------------- scratch (device globals; no runtime allocation) ------------
__device__ __align__(16) int   g_cnt_in [N_NODES];
__device__ __align__(16) int   g_cnt_out[N_NODES];
__device__ __align__(16) int   g_rank   [N_EDGES];      // within-dst edge rank
__device__ __align__(16) int   g_local  [N_NODES];      // per-block exclusive scan
__device__ __align__(16) int   g_blksum [512];
__device__ __align__(16) int   g_rowptr [N_NODES + 1];
__device__ __align__(16) int   g_srcsrt [N_EDGES];      // src ids grouped by dst
__device__ __align__(16) float g_ns [N_NODES];          // norm_src
__device__ __align__(16) float g_nd [N_NODES];          // norm_dst
__device__ __align__(16) float g_t  [N_NODES * 64];     // messages
__device__ __align__(16) float g_m  [N_NODES * 64];     // aggregated / activations
__device__ __align__(16) float g_h  [N_NODES * 128];    // 128-wide activations
__device__ __align__(16) float g_hg [N_GRAPHS * 64];    // pooled graph features

// ---------------- zero ---------------------------------------------------------
__global__ void k_zero() {
    int i = blockIdx.x * blockDim.x + threadIdx.x;
    if (i < N_NODES) { g_cnt_in[i] = 0; g_cnt_out[i] = 0; }
    if (i < N_GRAPHS * 64) g_hg[i] = 0.f;
}

// ---------------- degree histograms + free edge ranks ---------------------------
__global__ void k_hist(const int* __restrict__ src, const int* __restrict__ dst) {
    int i = blockIdx.x * blockDim.x + threadIdx.x;
    if (i < N_EDGES) {
        g_rank[i] = atomicAdd(&g_cnt_in[dst[i]], 1);   // rank is free byproduct
        atomicAdd(&g_cnt_out[src[i]], 1);
    }
}

// ---------------- 2-level exclusive scan of g_cnt_in → g_rowptr ----------------
__global__ void k_scan1() {
    __shared__ int sh[256];
    int i = blockIdx.x * 256 + threadIdx.x;
    int v = (i < N_NODES) ? g_cnt_in[i] : 0;
    sh[threadIdx.x] = v;
    __syncthreads();
#pragma unroll
    for (int off = 1; off < 256; off <<= 1) {
        int t = (threadIdx.x >= off) ? sh[threadIdx.x - off] : 0;
        __syncthreads();
        sh[threadIdx.x] += t;
        __syncthreads();
    }
    if (i < N_NODES) g_local[i] = sh[threadIdx.x] - v;   // exclusive
    if (threadIdx.x == 255) g_blksum[blockIdx.x] = sh[255];
}

__global__ void k_scan2() {
    __shared__ int sh[512];
    int t = threadIdx.x;
    int v = (t < NBLK) ? g_blksum[t] : 0;
    sh[t] = v;
    __syncthreads();
#pragma unroll
    for (int off = 1; off < 512; off <<= 1) {
        int u = (t >= off) ? sh[t - off] : 0;
        __syncthreads();
        sh[t] += u;
        __syncthreads();
    }
    if (t < NBLK) g_blksum[t] = sh[t] - v;               // exclusive
}

// scan3 + norms fused
__global__ void k_scan3() {
    int i = blockIdx.x * 256 + threadIdx.x;
    if (i < N_NODES) {
        g_rowptr[i] = g_local[i] + g_blksum[blockIdx.x];
        g_ns[i] = rsqrtf(fmaxf((float)g_cnt_out[i], 1.f));
        g_nd[i] = rsqrtf(fmaxf((float)g_cnt_in [i], 1.f));
    }
    if (i == 0) g_rowptr[N_NODES] = N_EDGES;
}

// ---------------- bucket fill: atomic-free -------------------------------------
__global__ void k_fill(const int* __restrict__ src, const int* __restrict__ dst) {
    int i = blockIdx.x * blockDim.x + threadIdx.x;
    if (i < N_EDGES) {
        int pos = __ldg(&g_rowptr[dst[i]]) + g_rank[i];
        g_srcsrt[pos] = src[i];
    }
}

// ---------------- register-tiled (row-scale) x matmul ---------------------------
// out[n, j] = act( (X[n,:] * scale[n]) @ W + bias[j] )
// Tile = 32 nodes (100000 % 32 == 0 after padding loop: 100000/32 = 3125 exact).
template <int DIN, int DOUT, bool RELU, bool HASBIAS>
__global__ void k_mm(const float* __restrict__ X, const float* __restrict__ scale,
                     const float* __restrict__ W, const float* __restrict__ bias,
                     float* __restrict__ out) {
    constexpr int K4  = DIN / 4;
    constexpr int J4  = DOUT / 4;           // 16 (DOUT=64) or 32 (DOUT=128)
    constexpr int NPT = J4 / 8;             // nodes per thread: 2 or 4
    __shared__ float4 sW[DIN][J4];          // W[k][j-group]
    __shared__ float4 sX[32][K4];           // scaled inputs, 32 nodes

    // load W (once per block)
    for (int i = threadIdx.x; i < DIN * J4; i += 256)
        ((float4*)sW)[i] = ((const float4*)W)[i];

    const int j4 = threadIdx.x % J4;
    const int ng = threadIdx.x / J4;        // node group

    float4 bj = make_float4(0.f, 0.f, 0.f, 0.f);
    if (HASBIAS) bj = ((const float4*)bias)[j4];

    for (int base = blockIdx.x * 32; base < N_NODES; base += gridDim.x * 32) {
        __syncthreads();
        // stage 32 scaled node rows (row-contiguous -> conflict-free)
        for (int i = threadIdx.x; i < 32 * DIN; i += 256) {
            int nl = i / DIN, k = i % DIN;
            int n = base + nl;
            ((float*)&sX[nl][0])[k] = X[(size_t)n * DIN + k] * scale[n];
        }
        __syncthreads();

        float4 acc[NPT];
#pragma unroll
        for (int t = 0; t < NPT; t++) acc[t] = bj;

#pragma unroll
        for (int k4 = 0; k4 < K4; k4++) {
            float4 w0 = sW[k4 * 4 + 0][j4];
            float4 w1 = sW[k4 * 4 + 1][j4];
            float4 w2 = sW[k4 * 4 + 2][j4];
            float4 w3 = sW[k4 * 4 + 3][j4];
#pragma unroll
            for (int t = 0; t < NPT; t++) {
                float4 xv = sX[ng * NPT + t][k4];
                acc[t].x = fmaf(xv.x, w0.x, acc[t].x);
                acc[t].y = fmaf(xv.x, w0.y, acc[t].y);
                acc[t].z = fmaf(xv.x, w0.z, acc[t].z);
                acc[t].w = fmaf(xv.x, w0.w, acc[t].w);
                acc[t].x = fmaf(xv.y, w1.x, acc[t].x);
                acc[t].y = fmaf(xv.y, w1.y, acc[t].y);
                acc[t].z = fmaf(xv.y, w1.z, acc[t].z);
                acc[t].w = fmaf(xv.y, w1.w, acc[t].w);
                acc[t].x = fmaf(xv.z, w2.x, acc[t].x);
                acc[t].y = fmaf(xv.z, w2.y, acc[t].y);
                acc[t].z = fmaf(xv.z, w2.z, acc[t].z);
                acc[t].w = fmaf(xv.z, w2.w, acc[t].w);
                acc[t].x = fmaf(xv.w, w3.x, acc[t].x);
                acc[t].y = fmaf(xv.w, w3.y, acc[t].y);
                acc[t].z = fmaf(xv.w, w3.z, acc[t].z);
                acc[t].w = fmaf(xv.w, w3.w, acc[t].w);
            }
        }

#pragma unroll
        for (int t = 0; t < NPT; t++) {
            int n = base + ng * NPT + t;
            float4 r = acc[t];
            if (RELU) {
                r.x = fmaxf(r.x, 0.f); r.y = fmaxf(r.y, 0.f);
                r.z = fmaxf(r.z, 0.f); r.w = fmaxf(r.w, 0.f);
            }
            ((float4*)out)[(size_t)n * J4 + j4] = r;
        }
    }
}

// ---------------- CSR gather + fused epilogue ------------------------------------
// MODE 0: out = sum                     MODE 1: out = relu(sum*nd + b) * ns
// MODE 2: out = relu(sum*nd + b)
template <int MODE>
__global__ void k_gather(const float* __restrict__ tin, const float* __restrict__ bias,
                         float* __restrict__ outp) {
    const int q = threadIdx.x & 15;              // float4 column within 64-float row
    const int n = blockIdx.x * 16 + (threadIdx.x >> 4);
    const unsigned gmask = 0xFFFFu << (threadIdx.x & 16);

    int beg = __ldg(&g_rowptr[n]);
    int end = __ldg(&g_rowptr[n + 1]);

    const float4* t4 = (const float4*)tin;
    float4 acc = make_float4(0.f, 0.f, 0.f, 0.f);

    int e = beg;
    for (; e + 4 <= end; e += 4) {
        int sv = 0;
        if (q < 4) sv = __ldg(&g_srcsrt[e + q]);
        int s0 = __shfl_sync(gmask, sv, 0, 16);
        int s1 = __shfl_sync(gmask, sv, 1, 16);
        int s2 = __shfl_sync(gmask, sv, 2, 16);
        int s3 = __shfl_sync(gmask, sv, 3, 16);
        float4 v0 = __ldg(&t4[(size_t)s0 * 16 + q]);
        float4 v1 = __ldg(&t4[(size_t)s1 * 16 + q]);
        float4 v2 = __ldg(&t4[(size_t)s2 * 16 + q]);
        float4 v3 = __ldg(&t4[(size_t)s3 * 16 + q]);
        acc.x += v0.x + v1.x; acc.y += v0.y + v1.y;
        acc.z += v0.z + v1.z; acc.w += v0.w + v1.w;
        acc.x += v2.x + v3.x; acc.y += v2.y + v3.y;
        acc.z += v2.z + v3.z; acc.w += v2.w + v3.w;
    }
    for (; e < end; e++) {
        int sv = 0;
        if (q == 0) sv = __ldg(&g_srcsrt[e]);
        int s0 = __shfl_sync(gmask, sv, 0, 16);
        float4 v0 = __ldg(&t4[(size_t)s0 * 16 + q]);
        acc.x += v0.x; acc.y += v0.y; acc.z += v0.z; acc.w += v0.w;
    }

    if (MODE == 0) {
        ((float4*)outp)[(size_t)n * 16 + q] = acc;
    } else {
        float nd = g_nd[n];
        float4 b = ((const float4*)bias)[q];
        float4 r;
        r.x = fmaxf(acc.x * nd + b.x, 0.f);
        r.y = fmaxf(acc.y * nd + b.y, 0.f);
        r.z = fmaxf(acc.z * nd + b.z, 0.f);
        r.w = fmaxf(acc.w * nd + b.w, 0.f);
        if (MODE == 1) {
            float ns = g_ns[n];
            r.x *= ns; r.y *= ns; r.z *= ns; r.w *= ns;
        }
        ((float4*)outp)[(size_t)n * 16 + q] = r;
    }
}

// ---------------- graph pooling (graph_ids sorted) -------------------------------
__global__ void k_pool(const float* __restrict__ h, const int* __restrict__ gid) {
    int f = threadIdx.x & 63;
    int r = threadIdx.x >> 6;
    int start = blockIdx.x * 512;
    int end = min(start + 512, N_NODES);
    float acc = 0.f;
    int cur = -1;
    for (int n = start + r; n < end; n += 4) {
        int g = gid[n];
        if (g != cur) {
            if (cur >= 0) atomicAdd(&g_hg[cur * 64 + f], acc);
            cur = g; acc = 0.f;
        }
        acc += h[(size_t)n * 64 + f];
    }
    if (cur >= 0) atomicAdd(&g_hg[cur * 64 + f], acc);
}

// ---------------- head: out = tanh(hg) @ Wd + bd ---------------------------------
__global__ void k_final(const float* __restrict__ Wd, const float* __restrict__ bd,
                        float* __restrict__ out) {
    int t = threadIdx.x;
    if (t >= N_GRAPHS * 10) return;
    int g = t / 10, c = t % 10;
    float acc = bd[c];
#pragma unroll 8
    for (int k = 0; k < 64; k++)
        acc += tanhf(g_hg[g * 64 + k]) * Wd[k * 10 + c];
    out[t] = acc;
}

// ---------------- host orchestration ----------------------------------------------
extern "C" void kernel_launch(void* const* d_in, const int* in_sizes, int n_in,
                              void* d_out, int out_size) {
    const float* in_feat = (const float*)d_in[0];
    const int*   src     = (const int*)  d_in[1];
    const int*   dst     = (const int*)  d_in[2];
    const int*   gid     = (const int*)  d_in[3];
    const float* W1 = (const float*)d_in[4];
    const float* b1 = (const float*)d_in[5];
    const float* W2 = (const float*)d_in[6];
    const float* b2 = (const float*)d_in[7];
    const float* W3 = (const float*)d_in[8];
    const float* b3 = (const float*)d_in[9];
    const float* Wd = (const float*)d_in[10];
    const float* bd = (const float*)d_in[11];
    float* out = (float*)d_out;

    float *p_t, *p_h, *p_m, *p_ns, *p_nd;
    cudaGetSymbolAddress((void**)&p_t,  g_t);
    cudaGetSymbolAddress((void**)&p_h,  g_h);
    cudaGetSymbolAddress((void**)&p_m,  g_m);
    cudaGetSymbolAddress((void**)&p_ns, g_ns);
    cudaGetSymbolAddress((void**)&p_nd, g_nd);

    const int TPB = 256;
    const int EDGE_BLKS = (N_EDGES + TPB - 1) / TPB;      // 12500
    const int GATH_BLKS = N_NODES / 16;                   // 6250 (exact)
    const int MM_GRID = 1184;                             // persistent, ~8/SM

    // ---- CSR build (reused by all 3 layers) ----
    k_zero <<<NBLK, TPB>>>();
    k_hist <<<EDGE_BLKS, TPB>>>(src, dst);
    k_scan1<<<NBLK, TPB>>>();
    k_scan2<<<1, 512>>>();
    k_scan3<<<NBLK, TPB>>>();
    k_fill <<<EDGE_BLKS, TPB>>>(src, dst);

    // ---- Layer 1: 128 -> 64, W before aggregation ----
    k_mm<128, 64, false, false><<<MM_GRID, TPB>>>(in_feat, p_ns, W1, nullptr, p_t);
    k_gather<1><<<GATH_BLKS, TPB>>>(p_t, b1, p_m);        // g_m = relu(agg*nd+b1)*ns

    // ---- Layer 2: 64 -> 128, aggregate first ----
    k_gather<0><<<GATH_BLKS, TPB>>>(p_m, nullptr, p_t);   // g_t = agg
    k_mm<64, 128, true, true><<<MM_GRID, TPB>>>(p_t, p_nd, W2, b2, p_h);

    // ---- Layer 3: 128 -> 64, W before aggregation ----
    k_mm<128, 64, false, false><<<MM_GRID, TPB>>>(p_h, p_ns, W3, nullptr, p_t);
    k_gather<2><<<GATH_BLKS, TPB>>>(p_t, b3, p_m);        // g_m = relu(agg*nd+b3)

    // ---- pooling + head ----
    k_pool <<<(N_NODES + 511) / 512, TPB>>>(p_m, gid);
    k_final<<<1, N_GRAPHS * 10>>>(Wd, bd, out);
}

// round 4
// speedup vs baseline: 2.5199x; 1.0587x over previous
#include <cuda_runtime.h>
#include <cuda_fp16.h>
#include <math.h>

#define N_NODES 100000
#define N_EDGES 3200000
#define N_GRAPHS 64
#define NBLK 391                    // ceil(N_NODES/256)

// ---------------- scratch (device globals; no runtime allocation) ------------
__device__ __align__(16) int    g_cnt_in [N_NODES];
__device__ __align__(16) int    g_cnt_out[N_NODES];
__device__ __align__(16) int    g_rank   [N_EDGES];     // within-dst edge rank
__device__ __align__(16) int    g_local  [N_NODES];     // per-block exclusive scan
__device__ __align__(16) int    g_blksum [512];
__device__ __align__(16) int    g_rowptr [N_NODES + 1];
__device__ __align__(16) int    g_srcsrt [N_EDGES];     // src ids grouped by dst
__device__ __align__(16) float  g_ns [N_NODES];         // norm_src
__device__ __align__(16) float  g_nd [N_NODES];         // norm_dst
__device__ __align__(16) __half g_th[N_NODES * 64];     // half message table
__device__ __align__(16) __half g_mh[N_NODES * 64];     // half activations (L1 out)
__device__ __align__(16) float  g_t  [N_NODES * 64];    // fp32 aggregates (L2 mm in)
__device__ __align__(16) float  g_m  [N_NODES * 64];    // fp32 final activations
__device__ __align__(16) float  g_h  [N_NODES * 128];   // 128-wide activations
__device__ __align__(16) float  g_hg [N_GRAPHS * 64];   // pooled graph features

// ---------------- zero ---------------------------------------------------------
__global__ void k_zero() {
    int i = blockIdx.x * blockDim.x + threadIdx.x;
    if (i < N_NODES) { g_cnt_in[i] = 0; g_cnt_out[i] = 0; }
    if (i < N_GRAPHS * 64) g_hg[i] = 0.f;
}

// ---------------- degree histograms + free edge ranks ---------------------------
__global__ void k_hist(const int* __restrict__ src, const int* __restrict__ dst) {
    int i = blockIdx.x * blockDim.x + threadIdx.x;
    if (i < N_EDGES) {
        g_rank[i] = atomicAdd(&g_cnt_in[dst[i]], 1);   // rank = free byproduct
        atomicAdd(&g_cnt_out[src[i]], 1);
    }
}

// ---------------- 2-level exclusive scan of g_cnt_in → g_rowptr ----------------
__global__ void k_scan1() {
    __shared__ int sh[256];
    int i = blockIdx.x * 256 + threadIdx.x;
    int v = (i < N_NODES) ? g_cnt_in[i] : 0;
    sh[threadIdx.x] = v;
    __syncthreads();
#pragma unroll
    for (int off = 1; off < 256; off <<= 1) {
        int t = (threadIdx.x >= off) ? sh[threadIdx.x - off] : 0;
        __syncthreads();
        sh[threadIdx.x] += t;
        __syncthreads();
    }
    if (i < N_NODES) g_local[i] = sh[threadIdx.x] - v;   // exclusive
    if (threadIdx.x == 255) g_blksum[blockIdx.x] = sh[255];
}

__global__ void k_scan2() {
    __shared__ int sh[512];
    int t = threadIdx.x;
    int v = (t < NBLK) ? g_blksum[t] : 0;
    sh[t] = v;
    __syncthreads();
#pragma unroll
    for (int off = 1; off < 512; off <<= 1) {
        int u = (t >= off) ? sh[t - off] : 0;
        __syncthreads();
        sh[t] += u;
        __syncthreads();
    }
    if (t < NBLK) g_blksum[t] = sh[t] - v;               // exclusive
}

// scan3 + norms fused
__global__ void k_scan3() {
    int i = blockIdx.x * 256 + threadIdx.x;
    if (i < N_NODES) {
        g_rowptr[i] = g_local[i] + g_blksum[blockIdx.x];
        g_ns[i] = rsqrtf(fmaxf((float)g_cnt_out[i], 1.f));
        g_nd[i] = rsqrtf(fmaxf((float)g_cnt_in [i], 1.f));
    }
    if (i == 0) g_rowptr[N_NODES] = N_EDGES;
}

// ---------------- bucket fill: atomic-free -------------------------------------
__global__ void k_fill(const int* __restrict__ src, const int* __restrict__ dst) {
    int i = blockIdx.x * blockDim.x + threadIdx.x;
    if (i < N_EDGES) {
        int pos = __ldg(&g_rowptr[dst[i]]) + g_rank[i];
        g_srcsrt[pos] = src[i];
    }
}

// ---------------- register-tiled (row-scale) x matmul ---------------------------
// out[n, j] = act( (X[n,:] * scale[n]) @ W + bias[j] ); OH -> store fp16
template <int DIN, int DOUT, bool RELU, bool HASBIAS, bool OH>
__global__ void k_mm(const float* __restrict__ X, const float* __restrict__ scale,
                     const float* __restrict__ W, const float* __restrict__ bias,
                     void* __restrict__ out) {
    constexpr int K4  = DIN / 4;
    constexpr int J4  = DOUT / 4;           // 16 (DOUT=64) or 32 (DOUT=128)
    constexpr int NPT = J4 / 8;             // nodes per thread: 2 or 4
    __shared__ float4 sW[DIN][J4];
    __shared__ float4 sX[32][K4];

    for (int i = threadIdx.x; i < DIN * J4; i += 256)
        ((float4*)sW)[i] = ((const float4*)W)[i];

    const int j4 = threadIdx.x % J4;
    const int ng = threadIdx.x / J4;

    float4 bj = make_float4(0.f, 0.f, 0.f, 0.f);
    if (HASBIAS) bj = ((const float4*)bias)[j4];

    for (int base = blockIdx.x * 32; base < N_NODES; base += gridDim.x * 32) {
        __syncthreads();
        for (int i = threadIdx.x; i < 32 * DIN; i += 256) {
            int nl = i / DIN, k = i % DIN;
            int n = base + nl;
            ((float*)&sX[nl][0])[k] = X[(size_t)n * DIN + k] * scale[n];
        }
        __syncthreads();

        float4 acc[NPT];
#pragma unroll
        for (int t = 0; t < NPT; t++) acc[t] = bj;

#pragma unroll
        for (int k4 = 0; k4 < K4; k4++) {
            float4 w0 = sW[k4 * 4 + 0][j4];
            float4 w1 = sW[k4 * 4 + 1][j4];
            float4 w2 = sW[k4 * 4 + 2][j4];
            float4 w3 = sW[k4 * 4 + 3][j4];
#pragma unroll
            for (int t = 0; t < NPT; t++) {
                float4 xv = sX[ng * NPT + t][k4];
                acc[t].x = fmaf(xv.x, w0.x, acc[t].x);
                acc[t].y = fmaf(xv.x, w0.y, acc[t].y);
                acc[t].z = fmaf(xv.x, w0.z, acc[t].z);
                acc[t].w = fmaf(xv.x, w0.w, acc[t].w);
                acc[t].x = fmaf(xv.y, w1.x, acc[t].x);
                acc[t].y = fmaf(xv.y, w1.y, acc[t].y);
                acc[t].z = fmaf(xv.y, w1.z, acc[t].z);
                acc[t].w = fmaf(xv.y, w1.w, acc[t].w);
                acc[t].x = fmaf(xv.z, w2.x, acc[t].x);
                acc[t].y = fmaf(xv.z, w2.y, acc[t].y);
                acc[t].z = fmaf(xv.z, w2.z, acc[t].z);
                acc[t].w = fmaf(xv.z, w2.w, acc[t].w);
                acc[t].x = fmaf(xv.w, w3.x, acc[t].x);
                acc[t].y = fmaf(xv.w, w3.y, acc[t].y);
                acc[t].z = fmaf(xv.w, w3.z, acc[t].z);
                acc[t].w = fmaf(xv.w, w3.w, acc[t].w);
            }
        }

#pragma unroll
        for (int t = 0; t < NPT; t++) {
            int n = base + ng * NPT + t;
            float4 r = acc[t];
            if (RELU) {
                r.x = fmaxf(r.x, 0.f); r.y = fmaxf(r.y, 0.f);
                r.z = fmaxf(r.z, 0.f); r.w = fmaxf(r.w, 0.f);
            }
            if (OH) {
                __half2 h0 = __float22half2_rn(make_float2(r.x, r.y));
                __half2 h1 = __float22half2_rn(make_float2(r.z, r.w));
                uint2 u;
                u.x = *(unsigned*)&h0; u.y = *(unsigned*)&h1;
                ((uint2*)out)[(size_t)n * J4 + j4] = u;
            } else {
                ((float4*)out)[(size_t)n * J4 + j4] = r;
            }
        }
    }
}

// ---------------- CSR gather (fp16 messages) + fused epilogue --------------------
// MODE 0: out(fp32) = sum
// MODE 1: out(fp16) = relu(sum*nd + b) * ns
// MODE 2: out(fp32) = relu(sum*nd + b)
template <int MODE>
__global__ void k_gather(const __half* __restrict__ tin, const float* __restrict__ bias,
                         void* __restrict__ outp) {
    const int lane = threadIdx.x & 31;
    const int q    = threadIdx.x & 7;             // uint4 (8-half) column in 64-half row
    const int n    = blockIdx.x * 32 + (threadIdx.x >> 3);
    const unsigned gmask = 0xFFu << (lane & 24);

    int beg = __ldg(&g_rowptr[n]);
    int end = __ldg(&g_rowptr[n + 1]);

    const uint4* t8 = (const uint4*)tin;
    float a0 = 0.f, a1 = 0.f, a2 = 0.f, a3 = 0.f;
    float a4 = 0.f, a5 = 0.f, a6 = 0.f, a7 = 0.f;

    int e = beg;
    for (; e + 4 <= end; e += 4) {
        int sv = (q < 4) ? __ldg(&g_srcsrt[e + q]) : 0;
#pragma unroll
        for (int u = 0; u < 4; u++) {
            int s = __shfl_sync(gmask, sv, u, 8);
            uint4 v = __ldg(&t8[(size_t)s * 8 + q]);
            float2 f0 = __half22float2(*(__half2*)&v.x);
            float2 f1 = __half22float2(*(__half2*)&v.y);
            float2 f2 = __half22float2(*(__half2*)&v.z);
            float2 f3 = __half22float2(*(__half2*)&v.w);
            a0 += f0.x; a1 += f0.y; a2 += f1.x; a3 += f1.y;
            a4 += f2.x; a5 += f2.y; a6 += f3.x; a7 += f3.y;
        }
    }
    for (; e < end; e++) {
        int sv = (q == 0) ? __ldg(&g_srcsrt[e]) : 0;
        int s = __shfl_sync(gmask, sv, 0, 8);
        uint4 v = __ldg(&t8[(size_t)s * 8 + q]);
        float2 f0 = __half22float2(*(__half2*)&v.x);
        float2 f1 = __half22float2(*(__half2*)&v.y);
        float2 f2 = __half22float2(*(__half2*)&v.z);
        float2 f3 = __half22float2(*(__half2*)&v.w);
        a0 += f0.x; a1 += f0.y; a2 += f1.x; a3 += f1.y;
        a4 += f2.x; a5 += f2.y; a6 += f3.x; a7 += f3.y;
    }

    if (MODE == 0) {
        float4* o4 = (float4*)outp;
        o4[(size_t)n * 16 + q * 2 + 0] = make_float4(a0, a1, a2, a3);
        o4[(size_t)n * 16 + q * 2 + 1] = make_float4(a4, a5, a6, a7);
    } else {
        float nd = g_nd[n];
        const float4* b4 = (const float4*)bias;
        float4 ba = b4[q * 2], bb = b4[q * 2 + 1];
        float r0 = fmaxf(a0 * nd + ba.x, 0.f);
        float r1 = fmaxf(a1 * nd + ba.y, 0.f);
        float r2 = fmaxf(a2 * nd + ba.z, 0.f);
        float r3 = fmaxf(a3 * nd + ba.w, 0.f);
        float r4 = fmaxf(a4 * nd + bb.x, 0.f);
        float r5 = fmaxf(a5 * nd + bb.y, 0.f);
        float r6 = fmaxf(a6 * nd + bb.z, 0.f);
        float r7 = fmaxf(a7 * nd + bb.w, 0.f);
        if (MODE == 1) {
            float ns = g_ns[n];
            r0 *= ns; r1 *= ns; r2 *= ns; r3 *= ns;
            r4 *= ns; r5 *= ns; r6 *= ns; r7 *= ns;
            __half2 h0 = __float22half2_rn(make_float2(r0, r1));
            __half2 h1 = __float22half2_rn(make_float2(r2, r3));
            __half2 h2 = __float22half2_rn(make_float2(r4, r5));
            __half2 h3 = __float22half2_rn(make_float2(r6, r7));
            uint4 u;
            u.x = *(unsigned*)&h0; u.y = *(unsigned*)&h1;
            u.z = *(unsigned*)&h2; u.w = *(unsigned*)&h3;
            ((uint4*)outp)[(size_t)n * 8 + q] = u;
        } else {
            float4* o4 = (float4*)outp;
            o4[(size_t)n * 16 + q * 2 + 0] = make_float4(r0, r1, r2, r3);
            o4[(size_t)n * 16 + q * 2 + 1] = make_float4(r4, r5, r6, r7);
        }
    }
}

// ---------------- graph pooling (graph_ids sorted) -------------------------------
__global__ void k_pool(const float* __restrict__ h, const int* __restrict__ gid) {
    int f = threadIdx.x & 63;
    int r = threadIdx.x >> 6;
    int start = blockIdx.x * 512;
    int end = min(start + 512, N_NODES);
    float acc = 0.f;
    int cur = -1;
    for (int n = start + r; n < end; n += 4) {
        int g = gid[n];
        if (g != cur) {
            if (cur >= 0) atomicAdd(&g_hg[cur * 64 + f], acc);
            cur = g; acc = 0.f;
        }
        acc += h[(size_t)n * 64 + f];
    }
    if (cur >= 0) atomicAdd(&g_hg[cur * 64 + f], acc);
}

// ---------------- head: out = tanh(hg) @ Wd + bd ---------------------------------
__global__ void k_final(const float* __restrict__ Wd, const float* __restrict__ bd,
                        float* __restrict__ out) {
    int t = threadIdx.x;
    if (t >= N_GRAPHS * 10) return;
    int g = t / 10, c = t % 10;
    float acc = bd[c];
#pragma unroll 8
    for (int k = 0; k < 64; k++)
        acc += tanhf(g_hg[g * 64 + k]) * Wd[k * 10 + c];
    out[t] = acc;
}

// ---------------- host orchestration ----------------------------------------------
extern "C" void kernel_launch(void* const* d_in, const int* in_sizes, int n_in,
                              void* d_out, int out_size) {
    const float* in_feat = (const float*)d_in[0];
    const int*   src     = (const int*)  d_in[1];
    const int*   dst     = (const int*)  d_in[2];
    const int*   gid     = (const int*)  d_in[3];
    const float* W1 = (const float*)d_in[4];
    const float* b1 = (const float*)d_in[5];
    const float* W2 = (const float*)d_in[6];
    const float* b2 = (const float*)d_in[7];
    const float* W3 = (const float*)d_in[8];
    const float* b3 = (const float*)d_in[9];
    const float* Wd = (const float*)d_in[10];
    const float* bd = (const float*)d_in[11];
    float* out = (float*)d_out;

    float *p_t, *p_h, *p_m, *p_ns, *p_nd;
    __half *p_th, *p_mh;
    cudaGetSymbolAddress((void**)&p_t,  g_t);
    cudaGetSymbolAddress((void**)&p_h,  g_h);
    cudaGetSymbolAddress((void**)&p_m,  g_m);
    cudaGetSymbolAddress((void**)&p_ns, g_ns);
    cudaGetSymbolAddress((void**)&p_nd, g_nd);
    cudaGetSymbolAddress((void**)&p_th, g_th);
    cudaGetSymbolAddress((void**)&p_mh, g_mh);

    const int TPB = 256;
    const int EDGE_BLKS = (N_EDGES + TPB - 1) / TPB;      // 12500
    const int GATH_BLKS = N_NODES / 32;                   // 3125 (exact)
    const int MM_GRID = 1184;

    // ---- CSR build (reused by all 3 layers) ----
    k_zero <<<NBLK, TPB>>>();
    k_hist <<<EDGE_BLKS, TPB>>>(src, dst);
    k_scan1<<<NBLK, TPB>>>();
    k_scan2<<<1, 512>>>();
    k_scan3<<<NBLK, TPB>>>();
    k_fill <<<EDGE_BLKS, TPB>>>(src, dst);

    // ---- Layer 1: 128 -> 64, W before aggregation, fp16 messages ----
    k_mm<128, 64, false, false, true><<<MM_GRID, TPB>>>(in_feat, p_ns, W1, nullptr, p_th);
    k_gather<1><<<GATH_BLKS, TPB>>>(p_th, b1, p_mh);      // fp16 out (L2 gather in)

    // ---- Layer 2: 64 -> 128, aggregate first ----
    k_gather<0><<<GATH_BLKS, TPB>>>(p_mh, nullptr, p_t);  // fp32 aggregates
    k_mm<64, 128, true, true, false><<<MM_GRID, TPB>>>(p_t, p_nd, W2, b2, p_h);

    // ---- Layer 3: 128 -> 64, W before aggregation, fp16 messages ----
    k_mm<128, 64, false, false, true><<<MM_GRID, TPB>>>(p_h, p_ns, W3, nullptr, p_th);
    k_gather<2><<<GATH_BLKS, TPB>>>(p_th, b3, p_m);       // fp32 final activations

    // ---- pooling + head ----
    k_pool <<<(N_NODES + 511) / 512, TPB>>>(p_m, gid);
    k_final<<<1, N_GRAPHS * 10>>>(Wd, bd, out);
}

// round 5
// speedup vs baseline: 2.7695x; 1.0991x over previous
#include <cuda_runtime.h>
#include <cuda_fp16.h>
#include <math.h>

#define N_NODES 100000
#define N_EDGES 3200000
#define N_GRAPHS 64
#define NBLK 391                    // ceil(N_NODES/256)

// ---------------- scratch (device globals; no runtime allocation) ------------
__device__ __align__(16) int    g_cnt_in [N_NODES];
__device__ __align__(16) int    g_cnt_out[N_NODES];
__device__ __align__(16) int    g_rank   [N_EDGES];
__device__ __align__(16) int    g_local  [N_NODES];
__device__ __align__(16) int    g_blksum [512];
__device__ __align__(16) int    g_rowptr [N_NODES + 1];
__device__ __align__(16) int    g_srcsrt [N_EDGES];
__device__ __align__(16) float  g_ns [N_NODES];
__device__ __align__(16) float  g_nd [N_NODES];
__device__ __align__(16) __half g_xh[(size_t)N_NODES * 128];      // scaled fp16 input
__device__ __align__(16) __half g_th[((size_t)N_NODES + 1) * 64]; // messages (+dummy)
__device__ __align__(16) __half g_mh[((size_t)N_NODES + 1) * 64]; // L1 activations (+dummy)
__device__ __align__(16) __half g_hh[(size_t)N_NODES * 128];      // L2 activations
__device__ __align__(16) float  g_m [(size_t)N_NODES * 64];       // final fp32 activations
__device__ __align__(16) float  g_hg[N_GRAPHS * 64];

// ---------------- zero ---------------------------------------------------------
__global__ void k_zero() {
    int i = blockIdx.x * blockDim.x + threadIdx.x;
    if (i < N_NODES) { g_cnt_in[i] = 0; g_cnt_out[i] = 0; }
    if (i < N_GRAPHS * 64) g_hg[i] = 0.f;
    if (i < 64) {                                  // dummy zero rows for gather tails
        g_th[(size_t)N_NODES * 64 + i] = __float2half(0.f);
        g_mh[(size_t)N_NODES * 64 + i] = __float2half(0.f);
    }
}

// ---------------- degree histograms + free edge ranks ---------------------------
__global__ void k_hist(const int* __restrict__ src, const int* __restrict__ dst) {
    int i = blockIdx.x * blockDim.x + threadIdx.x;
    if (i < N_EDGES) {
        g_rank[i] = atomicAdd(&g_cnt_in[dst[i]], 1);
        atomicAdd(&g_cnt_out[src[i]], 1);
    }
}

// ---------------- 2-level exclusive scan of g_cnt_in → g_rowptr ----------------
__global__ void k_scan1() {
    __shared__ int sh[256];
    int i = blockIdx.x * 256 + threadIdx.x;
    int v = (i < N_NODES) ? g_cnt_in[i] : 0;
    sh[threadIdx.x] = v;
    __syncthreads();
#pragma unroll
    for (int off = 1; off < 256; off <<= 1) {
        int t = (threadIdx.x >= off) ? sh[threadIdx.x - off] : 0;
        __syncthreads();
        sh[threadIdx.x] += t;
        __syncthreads();
    }
    if (i < N_NODES) g_local[i] = sh[threadIdx.x] - v;
    if (threadIdx.x == 255) g_blksum[blockIdx.x] = sh[255];
}

__global__ void k_scan2() {
    __shared__ int sh[512];
    int t = threadIdx.x;
    int v = (t < NBLK) ? g_blksum[t] : 0;
    sh[t] = v;
    __syncthreads();
#pragma unroll
    for (int off = 1; off < 512; off <<= 1) {
        int u = (t >= off) ? sh[t - off] : 0;
        __syncthreads();
        sh[t] += u;
        __syncthreads();
    }
    if (t < NBLK) g_blksum[t] = sh[t] - v;
}

__global__ void k_scan3() {
    int i = blockIdx.x * 256 + threadIdx.x;
    if (i < N_NODES) {
        g_rowptr[i] = g_local[i] + g_blksum[blockIdx.x];
        g_ns[i] = rsqrtf(fmaxf((float)g_cnt_out[i], 1.f));
        g_nd[i] = rsqrtf(fmaxf((float)g_cnt_in [i], 1.f));
    }
    if (i == 0) g_rowptr[N_NODES] = N_EDGES;
}

// ---------------- bucket fill: atomic-free -------------------------------------
__global__ void k_fill(const int* __restrict__ src, const int* __restrict__ dst) {
    int i = blockIdx.x * blockDim.x + threadIdx.x;
    if (i < N_EDGES) {
        int pos = __ldg(&g_rowptr[dst[i]]) + g_rank[i];
        g_srcsrt[pos] = src[i];
    }
}

// ---------------- fp32 -> fp16 input conversion with norm_src fold ---------------
__global__ void k_x16(const float* __restrict__ X) {
    int idx = blockIdx.x * blockDim.x + threadIdx.x;   // over N_NODES*16 (8 floats each)
    int n = idx >> 4, q = idx & 15;
    float ns = g_ns[n];
    const float4* p = (const float4*)(X + (size_t)n * 128) + q * 2;
    float4 u = __ldg(p), v = __ldg(p + 1);
    __half2 h0 = __float22half2_rn(make_float2(u.x * ns, u.y * ns));
    __half2 h1 = __float22half2_rn(make_float2(u.z * ns, u.w * ns));
    __half2 h2 = __float22half2_rn(make_float2(v.x * ns, v.y * ns));
    __half2 h3 = __float22half2_rn(make_float2(v.z * ns, v.w * ns));
    uint4 o;
    o.x = *(unsigned*)&h0; o.y = *(unsigned*)&h1;
    o.z = *(unsigned*)&h2; o.w = *(unsigned*)&h3;
    ((uint4*)g_xh)[(size_t)n * 16 + q] = o;
}

// ---------------- tensor-core matmul ---------------------------------------------
// out(fp16)[n, j] = postscale( act( X16[n,:] @ (W_hi+W_lo) + bias ) )
// W kept exact via hi/lo fp16 split (two chained MMAs).
template <int DIN, int DOUT, bool RELU, bool HASBIAS, bool SCALE>
__global__ void k_mmtc(const __half* __restrict__ X, const float* __restrict__ W,
                       const float* __restrict__ bias, const float* __restrict__ scale,
                       __half* __restrict__ out) {
    constexpr int XROW = DIN + 8;            // halves per smem row (pad)
    constexpr int WROW = DOUT + 1;           // half2 per packed-W row (pad)
    constexpr int K2   = DIN / 2;
    constexpr int NT   = DOUT / 8;
    extern __shared__ char smem[];
    __half*  sX   = (__half*)smem;
    __half2* sWhi = (__half2*)(smem + 128 * XROW * 2);
    __half2* sWlo = sWhi + K2 * WROW;

    const int tid = threadIdx.x;
    const int wid = tid >> 5, lane = tid & 31;
    const int g = lane >> 2, tig = lane & 3;

    // W -> hi/lo fp16, packed as (k pairs, n)
    for (int i = tid; i < DIN * DOUT; i += 256) {
        int k = i / DOUT, n = i % DOUT;
        float w = __ldg(&W[i]);
        __half hi = __float2half_rn(w);
        __half lo = __float2half_rn(w - __half2float(hi));
        ((__half*)sWhi)[((k >> 1) * WROW + n) * 2 + (k & 1)] = hi;
        ((__half*)sWlo)[((k >> 1) * WROW + n) * 2 + (k & 1)] = lo;
    }

    // stage 128 node rows of X (zero-fill past N_NODES)
    const int base = blockIdx.x * 128;
    constexpr int QPR = DIN / 8;             // uint4 per row
    for (int i = tid; i < 128 * QPR; i += 256) {
        int r = i / QPR, q = i % QPR;
        uint4 v = make_uint4(0u, 0u, 0u, 0u);
        int n = base + r;
        if (n < N_NODES) v = __ldg((const uint4*)(X + (size_t)n * DIN) + q);
        *(uint4*)(sX + r * XROW + q * 8) = v;
    }
    __syncthreads();

    float c[NT][4];
#pragma unroll
    for (int t = 0; t < NT; t++) { c[t][0] = c[t][1] = c[t][2] = c[t][3] = 0.f; }

    const __half* xw = sX + wid * 16 * XROW;   // this warp's 16 rows
#pragma unroll
    for (int k0 = 0; k0 < DIN; k0 += 16) {
        const __half* ap = xw + (size_t)(lane & 15) * XROW + k0 + ((lane >> 4) << 3);
        unsigned aaddr = (unsigned)__cvta_generic_to_shared(ap);
        unsigned a0, a1, a2, a3;
        asm volatile("ldmatrix.sync.aligned.m8n8.x4.shared.b16 {%0,%1,%2,%3}, [%4];"
                     : "=r"(a0), "=r"(a1), "=r"(a2), "=r"(a3) : "r"(aaddr));
#pragma unroll
        for (int t = 0; t < NT; t++) {
            unsigned bh0 = *(const unsigned*)&sWhi[(k0 / 2 + tig)     * WROW + t * 8 + g];
            unsigned bh1 = *(const unsigned*)&sWhi[(k0 / 2 + 4 + tig) * WROW + t * 8 + g];
            asm volatile("mma.sync.aligned.m16n8k16.row.col.f32.f16.f16.f32 "
                         "{%0,%1,%2,%3}, {%4,%5,%6,%7}, {%8,%9}, {%0,%1,%2,%3};"
                         : "+f"(c[t][0]), "+f"(c[t][1]), "+f"(c[t][2]), "+f"(c[t][3])
                         : "r"(a0), "r"(a1), "r"(a2), "r"(a3), "r"(bh0), "r"(bh1));
            unsigned bl0 = *(const unsigned*)&sWlo[(k0 / 2 + tig)     * WROW + t * 8 + g];
            unsigned bl1 = *(const unsigned*)&sWlo[(k0 / 2 + 4 + tig) * WROW + t * 8 + g];
            asm volatile("mma.sync.aligned.m16n8k16.row.col.f32.f16.f16.f32 "
                         "{%0,%1,%2,%3}, {%4,%5,%6,%7}, {%8,%9}, {%0,%1,%2,%3};"
                         : "+f"(c[t][0]), "+f"(c[t][1]), "+f"(c[t][2]), "+f"(c[t][3])
                         : "r"(a0), "r"(a1), "r"(a2), "r"(a3), "r"(bl0), "r"(bl1));
        }
    }

    // epilogue
    int n0 = base + wid * 16 + g;
    int n1 = n0 + 8;
    float s0 = 1.f, s1 = 1.f;
    if (SCALE) {
        if (n0 < N_NODES) s0 = __ldg(&scale[n0]);
        if (n1 < N_NODES) s1 = __ldg(&scale[n1]);
    }
#pragma unroll
    for (int t = 0; t < NT; t++) {
        int j0 = t * 8 + tig * 2;
        float bb0 = 0.f, bb1 = 0.f;
        if (HASBIAS) { bb0 = __ldg(&bias[j0]); bb1 = __ldg(&bias[j0 + 1]); }
        if (n0 < N_NODES) {
            float r0 = c[t][0] + bb0, r1 = c[t][1] + bb1;
            if (RELU) { r0 = fmaxf(r0, 0.f); r1 = fmaxf(r1, 0.f); }
            r0 *= s0; r1 *= s0;
            __half2 h = __float22half2_rn(make_float2(r0, r1));
            *(unsigned*)(out + (size_t)n0 * DOUT + j0) = *(unsigned*)&h;
        }
        if (n1 < N_NODES) {
            float r0 = c[t][2] + bb0, r1 = c[t][3] + bb1;
            if (RELU) { r0 = fmaxf(r0, 0.f); r1 = fmaxf(r1, 0.f); }
            r0 *= s1; r1 *= s1;
            __half2 h = __float22half2_rn(make_float2(r0, r1));
            *(unsigned*)(out + (size_t)n1 * DOUT + j0) = *(unsigned*)&h;
        }
    }
}

// ---------------- CSR gather: one warp per node (fp16 messages) -------------------
// MODE 0: out(fp16) = sum * nd                  (L2 mm input, nd folded)
// MODE 1: out(fp16) = relu(sum*nd + b) * ns     (L1 output)
// MODE 2: out(fp32) = relu(sum*nd + b)          (L3 output, pool input)
template <int MODE>
__global__ void k_gather(const __half* __restrict__ tin, const float* __restrict__ bias,
                         void* __restrict__ outp) {
    const int lane = threadIdx.x & 31;
    const int wid  = threadIdx.x >> 5;
    const int n    = blockIdx.x * 8 + wid;
    const int half_id = lane >> 4;          // 0: even edge, 1: odd edge
    const int col     = lane & 15;          // uint2 (4 halves) within 64-half row

    int beg = __ldg(&g_rowptr[n]);
    int end = __ldg(&g_rowptr[n + 1]);

    const uint2* t8 = (const uint2*)tin;
    float a0 = 0.f, a1 = 0.f, a2 = 0.f, a3 = 0.f;

    for (int e = beg; e < end; e += 4) {
        int sv = N_NODES;                                   // dummy zero row
        if (lane < 4 && e + lane < end) sv = __ldg(&g_srcsrt[e + lane]);
        int sA = __shfl_sync(0xFFFFFFFFu, sv, half_id);      // edges e+0 / e+1
        int sB = __shfl_sync(0xFFFFFFFFu, sv, 2 + half_id);  // edges e+2 / e+3
        uint2 vA = __ldg(&t8[(size_t)sA * 16 + col]);
        uint2 vB = __ldg(&t8[(size_t)sB * 16 + col]);
        float2 fA0 = __half22float2(*(__half2*)&vA.x);
        float2 fA1 = __half22float2(*(__half2*)&vA.y);
        float2 fB0 = __half22float2(*(__half2*)&vB.x);
        float2 fB1 = __half22float2(*(__half2*)&vB.y);
        a0 += fA0.x + fB0.x; a1 += fA0.y + fB0.y;
        a2 += fA1.x + fB1.x; a3 += fA1.y + fB1.y;
    }

    // fold the two half-warps (same columns)
    a0 += __shfl_xor_sync(0xFFFFFFFFu, a0, 16);
    a1 += __shfl_xor_sync(0xFFFFFFFFu, a1, 16);
    a2 += __shfl_xor_sync(0xFFFFFFFFu, a2, 16);
    a3 += __shfl_xor_sync(0xFFFFFFFFu, a3, 16);

    if (lane < 16) {
        float nd = __ldg(&g_nd[n]);
        if (MODE == 0) {
            __half2 h0 = __float22half2_rn(make_float2(a0 * nd, a1 * nd));
            __half2 h1 = __float22half2_rn(make_float2(a2 * nd, a3 * nd));
            uint2 u; u.x = *(unsigned*)&h0; u.y = *(unsigned*)&h1;
            ((uint2*)outp)[(size_t)n * 16 + col] = u;
        } else {
            float4 b = ((const float4*)bias)[col];
            float r0 = fmaxf(a0 * nd + b.x, 0.f);
            float r1 = fmaxf(a1 * nd + b.y, 0.f);
            float r2 = fmaxf(a2 * nd + b.z, 0.f);
            float r3 = fmaxf(a3 * nd + b.w, 0.f);
            if (MODE == 1) {
                float ns = __ldg(&g_ns[n]);
                r0 *= ns; r1 *= ns; r2 *= ns; r3 *= ns;
                __half2 h0 = __float22half2_rn(make_float2(r0, r1));
                __half2 h1 = __float22half2_rn(make_float2(r2, r3));
                uint2 u; u.x = *(unsigned*)&h0; u.y = *(unsigned*)&h1;
                ((uint2*)outp)[(size_t)n * 16 + col] = u;
            } else {
                ((float4*)outp)[(size_t)n * 16 + col] = make_float4(r0, r1, r2, r3);
            }
        }
    }
}

// ---------------- graph pooling (graph_ids sorted) -------------------------------
__global__ void k_pool(const float* __restrict__ h, const int* __restrict__ gid) {
    int f = threadIdx.x & 63;
    int r = threadIdx.x >> 6;
    int start = blockIdx.x * 512;
    int end = min(start + 512, N_NODES);
    float acc = 0.f;
    int cur = -1;
    for (int n = start + r; n < end; n += 4) {
        int g = gid[n];
        if (g != cur) {
            if (cur >= 0) atomicAdd(&g_hg[cur * 64 + f], acc);
            cur = g; acc = 0.f;
        }
        acc += h[(size_t)n * 64 + f];
    }
    if (cur >= 0) atomicAdd(&g_hg[cur * 64 + f], acc);
}

// ---------------- head: out = tanh(hg) @ Wd + bd ---------------------------------
__global__ void k_final(const float* __restrict__ Wd, const float* __restrict__ bd,
                        float* __restrict__ out) {
    int t = threadIdx.x;
    if (t >= N_GRAPHS * 10) return;
    int g = t / 10, c = t % 10;
    float acc = bd[c];
#pragma unroll 8
    for (int k = 0; k < 64; k++)
        acc += tanhf(g_hg[g * 64 + k]) * Wd[k * 10 + c];
    out[t] = acc;
}

// ---------------- host orchestration ----------------------------------------------
extern "C" void kernel_launch(void* const* d_in, const int* in_sizes, int n_in,
                              void* d_out, int out_size) {
    const float* in_feat = (const float*)d_in[0];
    const int*   src     = (const int*)  d_in[1];
    const int*   dst     = (const int*)  d_in[2];
    const int*   gid     = (const int*)  d_in[3];
    const float* W1 = (const float*)d_in[4];
    const float* b1 = (const float*)d_in[5];
    const float* W2 = (const float*)d_in[6];
    const float* b2 = (const float*)d_in[7];
    const float* W3 = (const float*)d_in[8];
    const float* b3 = (const float*)d_in[9];
    const float* Wd = (const float*)d_in[10];
    const float* bd = (const float*)d_in[11];
    float* out = (float*)d_out;

    float *p_m, *p_ns, *p_nd;
    __half *p_xh, *p_th, *p_mh, *p_hh;
    cudaGetSymbolAddress((void**)&p_m,  g_m);
    cudaGetSymbolAddress((void**)&p_ns, g_ns);
    cudaGetSymbolAddress((void**)&p_nd, g_nd);
    cudaGetSymbolAddress((void**)&p_xh, g_xh);
    cudaGetSymbolAddress((void**)&p_th, g_th);
    cudaGetSymbolAddress((void**)&p_mh, g_mh);
    cudaGetSymbolAddress((void**)&p_hh, g_hh);

    const int TPB = 256;
    const int EDGE_BLKS = (N_EDGES + TPB - 1) / TPB;      // 12500
    const int GATH_BLKS = N_NODES / 8;                    // 12500 (exact)
    const int MM_BLKS   = (N_NODES + 127) / 128;          // 782
    const int X16_BLKS  = N_NODES * 16 / TPB;             // 6250

    // dynamic smem sizes:  sX + 2 * packed W
    auto smem_sz = [](int DIN, int DOUT) {
        return 128 * (DIN + 8) * 2 + 2 * (DIN / 2) * (DOUT + 1) * 4;
    };
    const int SM1 = smem_sz(128, 64);    // 68096
    const int SM2 = smem_sz(64, 128);    // 51456
    const int SM3 = smem_sz(128, 64);    // 68096
    cudaFuncSetAttribute(k_mmtc<128, 64, false, false, false>,
                         cudaFuncAttributeMaxDynamicSharedMemorySize, SM1);
    cudaFuncSetAttribute(k_mmtc<64, 128, true, true, true>,
                         cudaFuncAttributeMaxDynamicSharedMemorySize, SM2);

    // ---- CSR build (reused by all 3 layers) ----
    k_zero <<<NBLK, TPB>>>();
    k_hist <<<EDGE_BLKS, TPB>>>(src, dst);
    k_scan1<<<NBLK, TPB>>>();
    k_scan2<<<1, 512>>>();
    k_scan3<<<NBLK, TPB>>>();
    k_fill <<<EDGE_BLKS, TPB>>>(src, dst);

    // ---- input -> fp16 with norm_src folded ----
    k_x16<<<X16_BLKS, TPB>>>(in_feat);

    // ---- Layer 1: 128 -> 64 (W before aggregation) ----
    k_mmtc<128, 64, false, false, false><<<MM_BLKS, TPB, SM1>>>(p_xh, W1, nullptr, nullptr, p_th);
    k_gather<1><<<GATH_BLKS, TPB>>>(p_th, b1, p_mh);      // relu(agg*nd+b1)*ns -> fp16

    // ---- Layer 2: 64 -> 128 (aggregate first) ----
    k_gather<0><<<GATH_BLKS, TPB>>>(p_mh, nullptr, p_th); // agg*nd -> fp16 (reuse g_th)
    k_mmtc<64, 128, true, true, true><<<MM_BLKS, TPB, SM2>>>(p_th, W2, b2, p_ns, p_hh);

    // ---- Layer 3: 128 -> 64 (W before aggregation) ----
    k_mmtc<128, 64, false, false, false><<<MM_BLKS, TPB, SM3>>>(p_hh, W3, nullptr, nullptr, p_th);
    k_gather<2><<<GATH_BLKS, TPB>>>(p_th, b3, p_m);       // relu(agg*nd+b3) -> fp32

    // ---- pooling + head ----
    k_pool <<<(N_NODES + 511) / 512, TPB>>>(p_m, gid);
    k_final<<<1, N_GRAPHS * 10>>>(Wd, bd, out);
}

// round 6
// speedup vs baseline: 2.8633x; 1.0339x over previous
#include <cuda_runtime.h>
#include <cuda_fp16.h>
#include <math.h>

#define N_NODES 100000
#define N_EDGES 3200000
#define N_GRAPHS 64
#define NBLK 391                    // ceil(N_NODES/256)

// ---------------- scratch (device globals; no runtime allocation) ------------
__device__ __align__(16) int    g_cnt_in [N_NODES];
__device__ __align__(16) int    g_cnt_out[N_NODES];
__device__ __align__(16) int    g_rank   [N_EDGES];
__device__ __align__(16) int    g_local  [N_NODES];
__device__ __align__(16) int    g_blksum [512];
__device__ __align__(16) int    g_rowptr [N_NODES + 1];
__device__ __align__(16) int    g_srcsrt [N_EDGES];
__device__ __align__(16) float  g_ns [N_NODES];
__device__ __align__(16) float  g_nd [N_NODES];
__device__ __align__(16) __half g_th[((size_t)N_NODES + 1) * 64]; // messages (+dummy)
__device__ __align__(16) __half g_mh[((size_t)N_NODES + 1) * 64]; // L1 act (+dummy)
__device__ __align__(16) __half g_hh[(size_t)N_NODES * 128];      // L2 activations
__device__ __align__(16) float  g_m [(size_t)N_NODES * 64];       // final fp32 act
__device__ __align__(16) float  g_hg[N_GRAPHS * 64];

// ---------------- zero ---------------------------------------------------------
__global__ void k_zero() {
    int i = blockIdx.x * blockDim.x + threadIdx.x;
    if (i < N_NODES) { g_cnt_in[i] = 0; g_cnt_out[i] = 0; }
    if (i < N_GRAPHS * 64) g_hg[i] = 0.f;
    if (i < 64) {                                  // dummy zero rows for gather tails
        g_th[(size_t)N_NODES * 64 + i] = __float2half(0.f);
        g_mh[(size_t)N_NODES * 64 + i] = __float2half(0.f);
    }
}

// ---------------- degree histograms + free edge ranks ---------------------------
__global__ void k_hist(const int* __restrict__ src, const int* __restrict__ dst) {
    int i = blockIdx.x * blockDim.x + threadIdx.x;
    if (i < N_EDGES) {
        g_rank[i] = atomicAdd(&g_cnt_in[dst[i]], 1);
        atomicAdd(&g_cnt_out[src[i]], 1);
    }
}

// ---------------- 2-level exclusive scan of g_cnt_in → g_rowptr ----------------
__global__ void k_scan1() {
    __shared__ int sh[256];
    int i = blockIdx.x * 256 + threadIdx.x;
    int v = (i < N_NODES) ? g_cnt_in[i] : 0;
    sh[threadIdx.x] = v;
    __syncthreads();
#pragma unroll
    for (int off = 1; off < 256; off <<= 1) {
        int t = (threadIdx.x >= off) ? sh[threadIdx.x - off] : 0;
        __syncthreads();
        sh[threadIdx.x] += t;
        __syncthreads();
    }
    if (i < N_NODES) g_local[i] = sh[threadIdx.x] - v;
    if (threadIdx.x == 255) g_blksum[blockIdx.x] = sh[255];
}

__global__ void k_scan2() {
    __shared__ int sh[512];
    int t = threadIdx.x;
    int v = (t < NBLK) ? g_blksum[t] : 0;
    sh[t] = v;
    __syncthreads();
#pragma unroll
    for (int off = 1; off < 512; off <<= 1) {
        int u = (t >= off) ? sh[t - off] : 0;
        __syncthreads();
        sh[t] += u;
        __syncthreads();
    }
    if (t < NBLK) g_blksum[t] = sh[t] - v;
}

__global__ void k_scan3() {
    int i = blockIdx.x * 256 + threadIdx.x;
    if (i < N_NODES) {
        g_rowptr[i] = g_local[i] + g_blksum[blockIdx.x];
        g_ns[i] = rsqrtf(fmaxf((float)g_cnt_out[i], 1.f));
        g_nd[i] = rsqrtf(fmaxf((float)g_cnt_in [i], 1.f));
    }
    if (i == 0) g_rowptr[N_NODES] = N_EDGES;
}

// ---------------- bucket fill: atomic-free -------------------------------------
__global__ void k_fill(const int* __restrict__ src, const int* __restrict__ dst) {
    int i = blockIdx.x * blockDim.x + threadIdx.x;
    if (i < N_EDGES) {
        int pos = __ldg(&g_rowptr[dst[i]]) + g_rank[i];
        g_srcsrt[pos] = src[i];
    }
}

// ---------------- tensor-core matmul ---------------------------------------------
// out(fp16)[n, j] = postscale( act( instage(X)[n,:] @ (W_hi+W_lo) + bias ) )
// W kept exact via hi/lo fp16 split (two chained MMAs).
// IN32: X is fp32 and in-scale (instage) multiplies by inscale[n] during staging.
template <int DIN, int DOUT, bool RELU, bool HASBIAS, bool SCALE, bool IN32>
__global__ void k_mmtc(const void* __restrict__ Xv, const float* __restrict__ W,
                       const float* __restrict__ bias, const float* __restrict__ scale,
                       const float* __restrict__ inscale, __half* __restrict__ out) {
    constexpr int XROW = DIN + 8;            // halves per smem row (pad)
    constexpr int WROW = DOUT + 1;           // half2 per packed-W row (pad)
    constexpr int K2   = DIN / 2;
    constexpr int NT   = DOUT / 8;
    extern __shared__ char smem[];
    __half*  sX   = (__half*)smem;
    __half2* sWhi = (__half2*)(smem + 128 * XROW * 2);
    __half2* sWlo = sWhi + K2 * WROW;

    const int tid = threadIdx.x;
    const int wid = tid >> 5, lane = tid & 31;
    const int g = lane >> 2, tig = lane & 3;

    // W -> hi/lo fp16, packed as (k pairs, n)
    for (int i = tid; i < DIN * DOUT; i += 256) {
        int k = i / DOUT, n = i % DOUT;
        float w = __ldg(&W[i]);
        __half hi = __float2half_rn(w);
        __half lo = __float2half_rn(w - __half2float(hi));
        ((__half*)sWhi)[((k >> 1) * WROW + n) * 2 + (k & 1)] = hi;
        ((__half*)sWlo)[((k >> 1) * WROW + n) * 2 + (k & 1)] = lo;
    }

    // stage 128 node rows of X (zero-fill past N_NODES)
    const int base = blockIdx.x * 128;
    constexpr int QPR = DIN / 8;             // 8-half groups per row
    for (int i = tid; i < 128 * QPR; i += 256) {
        int r = i / QPR, q = i % QPR;
        int n = base + r;
        uint4 v = make_uint4(0u, 0u, 0u, 0u);
        if (n < N_NODES) {
            if (IN32) {
                const float* X = (const float*)Xv;
                float s = __ldg(&inscale[n]);
                const float4* p = (const float4*)(X + (size_t)n * DIN) + q * 2;
                float4 u0 = __ldg(p), u1 = __ldg(p + 1);
                __half2 h0 = __float22half2_rn(make_float2(u0.x * s, u0.y * s));
                __half2 h1 = __float22half2_rn(make_float2(u0.z * s, u0.w * s));
                __half2 h2 = __float22half2_rn(make_float2(u1.x * s, u1.y * s));
                __half2 h3 = __float22half2_rn(make_float2(u1.z * s, u1.w * s));
                v.x = *(unsigned*)&h0; v.y = *(unsigned*)&h1;
                v.z = *(unsigned*)&h2; v.w = *(unsigned*)&h3;
            } else {
                const __half* X = (const __half*)Xv;
                v = __ldg((const uint4*)(X + (size_t)n * DIN) + q);
            }
        }
        *(uint4*)(sX + r * XROW + q * 8) = v;
    }
    __syncthreads();

    float c[NT][4];
#pragma unroll
    for (int t = 0; t < NT; t++) { c[t][0] = c[t][1] = c[t][2] = c[t][3] = 0.f; }

    const __half* xw = sX + wid * 16 * XROW;   // this warp's 16 rows
#pragma unroll
    for (int k0 = 0; k0 < DIN; k0 += 16) {
        const __half* ap = xw + (size_t)(lane & 15) * XROW + k0 + ((lane >> 4) << 3);
        unsigned aaddr = (unsigned)__cvta_generic_to_shared(ap);
        unsigned a0, a1, a2, a3;
        asm volatile("ldmatrix.sync.aligned.m8n8.x4.shared.b16 {%0,%1,%2,%3}, [%4];"
                     : "=r"(a0), "=r"(a1), "=r"(a2), "=r"(a3) : "r"(aaddr));
#pragma unroll
        for (int t = 0; t < NT; t++) {
            unsigned bh0 = *(const unsigned*)&sWhi[(k0 / 2 + tig)     * WROW + t * 8 + g];
            unsigned bh1 = *(const unsigned*)&sWhi[(k0 / 2 + 4 + tig) * WROW + t * 8 + g];
            asm volatile("mma.sync.aligned.m16n8k16.row.col.f32.f16.f16.f32 "
                         "{%0,%1,%2,%3}, {%4,%5,%6,%7}, {%8,%9}, {%0,%1,%2,%3};"
                         : "+f"(c[t][0]), "+f"(c[t][1]), "+f"(c[t][2]), "+f"(c[t][3])
                         : "r"(a0), "r"(a1), "r"(a2), "r"(a3), "r"(bh0), "r"(bh1));
            unsigned bl0 = *(const unsigned*)&sWlo[(k0 / 2 + tig)     * WROW + t * 8 + g];
            unsigned bl1 = *(const unsigned*)&sWlo[(k0 / 2 + 4 + tig) * WROW + t * 8 + g];
            asm volatile("mma.sync.aligned.m16n8k16.row.col.f32.f16.f16.f32 "
                         "{%0,%1,%2,%3}, {%4,%5,%6,%7}, {%8,%9}, {%0,%1,%2,%3};"
                         : "+f"(c[t][0]), "+f"(c[t][1]), "+f"(c[t][2]), "+f"(c[t][3])
                         : "r"(a0), "r"(a1), "r"(a2), "r"(a3), "r"(bl0), "r"(bl1));
        }
    }

    // epilogue
    int n0 = base + wid * 16 + g;
    int n1 = n0 + 8;
    float s0 = 1.f, s1 = 1.f;
    if (SCALE) {
        if (n0 < N_NODES) s0 = __ldg(&scale[n0]);
        if (n1 < N_NODES) s1 = __ldg(&scale[n1]);
    }
#pragma unroll
    for (int t = 0; t < NT; t++) {
        int j0 = t * 8 + tig * 2;
        float bb0 = 0.f, bb1 = 0.f;
        if (HASBIAS) { bb0 = __ldg(&bias[j0]); bb1 = __ldg(&bias[j0 + 1]); }
        if (n0 < N_NODES) {
            float r0 = c[t][0] + bb0, r1 = c[t][1] + bb1;
            if (RELU) { r0 = fmaxf(r0, 0.f); r1 = fmaxf(r1, 0.f); }
            r0 *= s0; r1 *= s0;
            __half2 h = __float22half2_rn(make_float2(r0, r1));
            *(unsigned*)(out + (size_t)n0 * DOUT + j0) = *(unsigned*)&h;
        }
        if (n1 < N_NODES) {
            float r0 = c[t][2] + bb0, r1 = c[t][3] + bb1;
            if (RELU) { r0 = fmaxf(r0, 0.f); r1 = fmaxf(r1, 0.f); }
            r0 *= s1; r1 *= s1;
            __half2 h = __float22half2_rn(make_float2(r0, r1));
            *(unsigned*)(out + (size_t)n1 * DOUT + j0) = *(unsigned*)&h;
        }
    }
}

// ---------------- CSR gather: one warp per node, 8-edge unroll (MLP=4) ------------
// MODE 0: out(fp16) = sum * nd                  (L2 mm input, nd folded)
// MODE 1: out(fp16) = relu(sum*nd + b) * ns     (L1 output)
// MODE 2: out(fp32) = relu(sum*nd + b)          (L3 output, pool input)
template <int MODE>
__global__ void k_gather(const __half* __restrict__ tin, const float* __restrict__ bias,
                         void* __restrict__ outp) {
    const int lane = threadIdx.x & 31;
    const int wid  = threadIdx.x >> 5;
    const int n    = blockIdx.x * 8 + wid;
    const int half_id = lane >> 4;          // 0: even edge, 1: odd edge (of a pair)
    const int col     = lane & 15;          // uint2 (4 halves) within 64-half row

    int beg = __ldg(&g_rowptr[n]);
    int end = __ldg(&g_rowptr[n + 1]);

    const uint2* t8 = (const uint2*)tin;
    float a0 = 0.f, a1 = 0.f, a2 = 0.f, a3 = 0.f;

    for (int e = beg; e < end; e += 8) {
        int sv = N_NODES;                                   // dummy zero row
        if (lane < 8 && e + lane < end) sv = __ldg(&g_srcsrt[e + lane]);
        int sA = __shfl_sync(0xFFFFFFFFu, sv, half_id);      // edges e+0 / e+1
        int sB = __shfl_sync(0xFFFFFFFFu, sv, 2 + half_id);  // edges e+2 / e+3
        int sC = __shfl_sync(0xFFFFFFFFu, sv, 4 + half_id);  // edges e+4 / e+5
        int sD = __shfl_sync(0xFFFFFFFFu, sv, 6 + half_id);  // edges e+6 / e+7
        uint2 vA = __ldg(&t8[(size_t)sA * 16 + col]);
        uint2 vB = __ldg(&t8[(size_t)sB * 16 + col]);
        uint2 vC = __ldg(&t8[(size_t)sC * 16 + col]);
        uint2 vD = __ldg(&t8[(size_t)sD * 16 + col]);
        float2 f;
        f = __half22float2(*(__half2*)&vA.x); a0 += f.x; a1 += f.y;
        f = __half22float2(*(__half2*)&vA.y); a2 += f.x; a3 += f.y;
        f = __half22float2(*(__half2*)&vB.x); a0 += f.x; a1 += f.y;
        f = __half22float2(*(__half2*)&vB.y); a2 += f.x; a3 += f.y;
        f = __half22float2(*(__half2*)&vC.x); a0 += f.x; a1 += f.y;
        f = __half22float2(*(__half2*)&vC.y); a2 += f.x; a3 += f.y;
        f = __half22float2(*(__half2*)&vD.x); a0 += f.x; a1 += f.y;
        f = __half22float2(*(__half2*)&vD.y); a2 += f.x; a3 += f.y;
    }

    // fold the two half-warps (same columns)
    a0 += __shfl_xor_sync(0xFFFFFFFFu, a0, 16);
    a1 += __shfl_xor_sync(0xFFFFFFFFu, a1, 16);
    a2 += __shfl_xor_sync(0xFFFFFFFFu, a2, 16);
    a3 += __shfl_xor_sync(0xFFFFFFFFu, a3, 16);

    if (lane < 16) {
        float nd = __ldg(&g_nd[n]);
        if (MODE == 0) {
            __half2 h0 = __float22half2_rn(make_float2(a0 * nd, a1 * nd));
            __half2 h1 = __float22half2_rn(make_float2(a2 * nd, a3 * nd));
            uint2 u; u.x = *(unsigned*)&h0; u.y = *(unsigned*)&h1;
            ((uint2*)outp)[(size_t)n * 16 + col] = u;
        } else {
            float4 b = ((const float4*)bias)[col];
            float r0 = fmaxf(a0 * nd + b.x, 0.f);
            float r1 = fmaxf(a1 * nd + b.y, 0.f);
            float r2 = fmaxf(a2 * nd + b.z, 0.f);
            float r3 = fmaxf(a3 * nd + b.w, 0.f);
            if (MODE == 1) {
                float ns = __ldg(&g_ns[n]);
                r0 *= ns; r1 *= ns; r2 *= ns; r3 *= ns;
                __half2 h0 = __float22half2_rn(make_float2(r0, r1));
                __half2 h1 = __float22half2_rn(make_float2(r2, r3));
                uint2 u; u.x = *(unsigned*)&h0; u.y = *(unsigned*)&h1;
                ((uint2*)outp)[(size_t)n * 16 + col] = u;
            } else {
                ((float4*)outp)[(size_t)n * 16 + col] = make_float4(r0, r1, r2, r3);
            }
        }
    }
}

// ---------------- graph pooling (graph_ids sorted) -------------------------------
__global__ void k_pool(const float* __restrict__ h, const int* __restrict__ gid) {
    int f = threadIdx.x & 63;
    int r = threadIdx.x >> 6;
    int start = blockIdx.x * 512;
    int end = min(start + 512, N_NODES);
    float acc = 0.f;
    int cur = -1;
    for (int n = start + r; n < end; n += 4) {
        int g = gid[n];
        if (g != cur) {
            if (cur >= 0) atomicAdd(&g_hg[cur * 64 + f], acc);
            cur = g; acc = 0.f;
        }
        acc += h[(size_t)n * 64 + f];
    }
    if (cur >= 0) atomicAdd(&g_hg[cur * 64 + f], acc);
}

// ---------------- head: out = tanh(hg) @ Wd + bd ---------------------------------
__global__ void k_final(const float* __restrict__ Wd, const float* __restrict__ bd,
                        float* __restrict__ out) {
    int t = threadIdx.x;
    if (t >= N_GRAPHS * 10) return;
    int g = t / 10, c = t % 10;
    float acc = bd[c];
#pragma unroll 8
    for (int k = 0; k < 64; k++)
        acc += tanhf(g_hg[g * 64 + k]) * Wd[k * 10 + c];
    out[t] = acc;
}

// ---------------- host orchestration ----------------------------------------------
extern "C" void kernel_launch(void* const* d_in, const int* in_sizes, int n_in,
                              void* d_out, int out_size) {
    const float* in_feat = (const float*)d_in[0];
    const int*   src     = (const int*)  d_in[1];
    const int*   dst     = (const int*)  d_in[2];
    const int*   gid     = (const int*)  d_in[3];
    const float* W1 = (const float*)d_in[4];
    const float* b1 = (const float*)d_in[5];
    const float* W2 = (const float*)d_in[6];
    const float* b2 = (const float*)d_in[7];
    const float* W3 = (const float*)d_in[8];
    const float* b3 = (const float*)d_in[9];
    const float* Wd = (const float*)d_in[10];
    const float* bd = (const float*)d_in[11];
    float* out = (float*)d_out;

    float *p_m, *p_ns, *p_nd;
    __half *p_th, *p_mh, *p_hh;
    cudaGetSymbolAddress((void**)&p_m,  g_m);
    cudaGetSymbolAddress((void**)&p_ns, g_ns);
    cudaGetSymbolAddress((void**)&p_nd, g_nd);
    cudaGetSymbolAddress((void**)&p_th, g_th);
    cudaGetSymbolAddress((void**)&p_mh, g_mh);
    cudaGetSymbolAddress((void**)&p_hh, g_hh);

    const int TPB = 256;
    const int EDGE_BLKS = (N_EDGES + TPB - 1) / TPB;      // 12500
    const int GATH_BLKS = N_NODES / 8;                    // 12500 (exact)
    const int MM_BLKS   = (N_NODES + 127) / 128;          // 782

    auto smem_sz = [](int DIN, int DOUT) {
        return 128 * (DIN + 8) * 2 + 2 * (DIN / 2) * (DOUT + 1) * 4;
    };
    const int SM1 = smem_sz(128, 64);
    const int SM2 = smem_sz(64, 128);
    cudaFuncSetAttribute(k_mmtc<128, 64, false, false, false, true>,
                         cudaFuncAttributeMaxDynamicSharedMemorySize, SM1);
    cudaFuncSetAttribute(k_mmtc<64, 128, true, true, true, false>,
                         cudaFuncAttributeMaxDynamicSharedMemorySize, SM2);
    cudaFuncSetAttribute(k_mmtc<128, 64, false, false, false, false>,
                         cudaFuncAttributeMaxDynamicSharedMemorySize, SM1);

    // ---- CSR build (reused by all 3 layers) ----
    k_zero <<<NBLK, TPB>>>();
    k_hist <<<EDGE_BLKS, TPB>>>(src, dst);
    k_scan1<<<NBLK, TPB>>>();
    k_scan2<<<1, 512>>>();
    k_scan3<<<NBLK, TPB>>>();
    k_fill <<<EDGE_BLKS, TPB>>>(src, dst);

    // ---- Layer 1: 128 -> 64 (fp32 in, ns folded at staging; W before aggregation) ----
    k_mmtc<128, 64, false, false, false, true><<<MM_BLKS, TPB, SM1>>>(
        in_feat, W1, nullptr, nullptr, p_ns, p_th);
    k_gather<1><<<GATH_BLKS, TPB>>>(p_th, b1, p_mh);      // relu(agg*nd+b1)*ns -> fp16

    // ---- Layer 2: 64 -> 128 (aggregate first) ----
    k_gather<0><<<GATH_BLKS, TPB>>>(p_mh, nullptr, p_th); // agg*nd -> fp16 (reuse g_th)
    k_mmtc<64, 128, true, true, true, false><<<MM_BLKS, TPB, SM2>>>(
        p_th, W2, b2, p_ns, nullptr, p_hh);

    // ---- Layer 3: 128 -> 64 (W before aggregation) ----
    k_mmtc<128, 64, false, false, false, false><<<MM_BLKS, TPB, SM1>>>(
        p_hh, W3, nullptr, nullptr, nullptr, p_th);
    k_gather<2><<<GATH_BLKS, TPB>>>(p_th, b3, p_m);       // relu(agg*nd+b3) -> fp32

    // ---- pooling + head ----
    k_pool <<<(N_NODES + 511) / 512, TPB>>>(p_m, gid);
    k_final<<<1, N_GRAPHS * 10>>>(Wd, bd, out);
}